// round 1
// baseline (speedup 1.0000x reference)
#include <cuda_runtime.h>
#include <cuda_bf16.h>
#include <math.h>

// Problem constants (fixed shapes for this problem instance)
#define NN 50000      // nodes
#define NE 800000     // edges
#define NODE_F 128
#define EDGE_F 32
#define TIME_D 16
#define MEM_D 128
#define GATE3 384     // 3*MEM_D
#define EPG 4         // edges per warp group in edge kernel

// ---------------- device scratch (no allocations allowed) ----------------
__device__ float g_pre [NN * 128];    // x @ W1a + b1  (per-node precomputed msg term)
__device__ float g_agg [NN * 128];    // sum of relu(h1) per target node
__device__ float g_cnt [NN];          // in-degree (float)
__device__ float g_invc[NN];          // 1/max(cnt,1)
__device__ float g_Wc  [128 * 384];   // W2 @ W_ih^T  combined, layout [k=128][o=384]
__device__ float g_cvec[384];         // b2 @ W_ih^T
__device__ float g_owT [128 * 128];   // out_w transposed -> [k][o]
__device__ float g_gi  [NN * 384];    // gate preactivations
__device__ float g_mem [NN * 128];    // GRU memory

// ---------------- prep: combined weights + transpose ----------------
__global__ void prep_kernel(const float* __restrict__ msg_w2,
                            const float* __restrict__ msg_b2,
                            const float* __restrict__ w_ih,
                            const float* __restrict__ out_w) {
    int idx = blockIdx.x * blockDim.x + threadIdx.x;
    if (idx < 128 * 384) {
        int i = idx / 384, o = idx % 384;
        const float* a = msg_w2 + i * 128;
        const float* b = w_ih + o * 128;
        float s = 0.f;
        #pragma unroll 8
        for (int k = 0; k < 128; k++) s = fmaf(a[k], b[k], s);
        g_Wc[i * 384 + o] = s;
    } else if (idx < 128 * 384 + 384) {
        int o = idx - 128 * 384;
        const float* b = w_ih + o * 128;
        float s = 0.f;
        #pragma unroll 8
        for (int k = 0; k < 128; k++) s = fmaf(msg_b2[k], b[k], s);
        g_cvec[o] = s;
    } else if (idx < 128 * 384 + 384 + 128 * 128) {
        int j = idx - (128 * 384 + 384);
        int k = j / 128, o = j % 128;
        g_owT[k * 128 + o] = out_w[o * 128 + k];
    }
}

// ---------------- generic tiled fp32 GEMM: C[M,N] = rowscale(A[M,128]) @ B[128,N] + bias ----------------
// BM=64, BN=128 (per grid.y block), BK=16, 256 threads, 8x4 microtile per thread.
__global__ void gemm128_kernel(const float* __restrict__ A,
                               const float* __restrict__ B,
                               const float* __restrict__ bias,
                               const float* __restrict__ rowscale,
                               float* __restrict__ C,
                               int M, int N) {
    __shared__ float As[64 * 16];
    __shared__ float Bs[16 * 128];
    const int t = threadIdx.x;
    const int m0 = blockIdx.x * 64;
    const int n0 = blockIdx.y * 128;
    const int cgrp = t & 31;   // columns 4*cgrp..4*cgrp+3
    const int rgrp = t >> 5;   // rows rgrp*8 .. rgrp*8+7

    float4 acc[8];
    #pragma unroll
    for (int i = 0; i < 8; i++) acc[i] = make_float4(0.f, 0.f, 0.f, 0.f);

    const int arow = t >> 2;       // 0..63
    const int ac4  = t & 3;        // which float4 within 16-col chunk
    const int brow1 = t >> 5, bc1 = t & 31;
    const int brow2 = (t + 256) >> 5, bc2 = (t + 256) & 31;

    for (int kk0 = 0; kk0 < 128; kk0 += 16) {
        // load A tile 64x16
        {
            int gm = m0 + arow;
            float4 v = make_float4(0.f, 0.f, 0.f, 0.f);
            if (gm < M) {
                v = reinterpret_cast<const float4*>(A + (size_t)gm * 128 + kk0)[ac4];
                if (rowscale) {
                    float rs = rowscale[gm];
                    v.x *= rs; v.y *= rs; v.z *= rs; v.w *= rs;
                }
            }
            reinterpret_cast<float4*>(As)[arow * 4 + ac4] = v;
        }
        // load B tile 16x128
        reinterpret_cast<float4*>(Bs)[t] =
            reinterpret_cast<const float4*>(B + (size_t)(kk0 + brow1) * N + n0)[bc1];
        reinterpret_cast<float4*>(Bs)[t + 256] =
            reinterpret_cast<const float4*>(B + (size_t)(kk0 + brow2) * N + n0)[bc2];
        __syncthreads();

        #pragma unroll
        for (int kk = 0; kk < 16; kk++) {
            float4 bv = reinterpret_cast<const float4*>(Bs)[kk * 32 + cgrp];
            #pragma unroll
            for (int i = 0; i < 8; i++) {
                float a = As[(rgrp * 8 + i) * 16 + kk];
                acc[i].x = fmaf(a, bv.x, acc[i].x);
                acc[i].y = fmaf(a, bv.y, acc[i].y);
                acc[i].z = fmaf(a, bv.z, acc[i].z);
                acc[i].w = fmaf(a, bv.w, acc[i].w);
            }
        }
        __syncthreads();
    }

    float4 bv = reinterpret_cast<const float4*>(bias + n0)[cgrp];
    #pragma unroll
    for (int i = 0; i < 8; i++) {
        int gm = m0 + rgrp * 8 + i;
        if (gm < M) {
            float4 v = acc[i];
            v.x += bv.x; v.y += bv.y; v.z += bv.z; v.w += bv.w;
            reinterpret_cast<float4*>(C + (size_t)gm * N + n0)[cgrp] = v;
        }
    }
}

// ---------------- edge kernel: h1 = relu(pre[src] + ea@W1b + te@W1c); scatter-add ----------------
__global__ void __launch_bounds__(256) edge_kernel(
    const float* __restrict__ edge_attr,
    const float* __restrict__ t_arr,
    const int*   __restrict__ src_idx,
    const int*   __restrict__ tgt_idx,
    const float* __restrict__ msg_w1,
    const float* __restrict__ time_w,
    const float* __restrict__ time_b,
    int E)
{
    // shared: rows 128..175 of msg_w1 (edge_attr part 32 rows + time part 16 rows), float4 per 4 cols
    __shared__ float4 sW[48 * 32];
    __shared__ float stw[16], stb[16];
    const int tid = threadIdx.x;
    for (int i = tid; i < 48 * 32; i += 256) {
        int r = i >> 5, c = i & 31;
        sW[i] = reinterpret_cast<const float4*>(msg_w1 + (size_t)(128 + r) * 128)[c];
    }
    if (tid < 16) { stw[tid] = time_w[tid]; stb[tid] = time_b[tid]; }
    __syncthreads();

    const int lane = tid & 31;
    const int warp = blockIdx.x * 8 + (tid >> 5);
    const int e0 = warp * EPG;
    if (e0 >= E) return;

    float ea[EPG], te[EPG];
    int tgts[EPG];
    float4 acc[EPG];
    #pragma unroll
    for (int i = 0; i < EPG; i++) {
        int e = e0 + i;
        ea[i] = edge_attr[(size_t)e * 32 + lane];
        float tv = t_arr[e];
        te[i] = (lane < 16) ? cosf(fmaf(tv, stw[lane], stb[lane])) : 0.f;
        int s = src_idx[e];
        tgts[i] = tgt_idx[e];
        acc[i] = reinterpret_cast<const float4*>(g_pre + (size_t)s * 128)[lane];
    }

    #pragma unroll 8
    for (int k = 0; k < 32; k++) {
        float4 w = sW[k * 32 + lane];
        #pragma unroll
        for (int i = 0; i < EPG; i++) {
            float a = __shfl_sync(0xffffffffu, ea[i], k);
            acc[i].x = fmaf(a, w.x, acc[i].x);
            acc[i].y = fmaf(a, w.y, acc[i].y);
            acc[i].z = fmaf(a, w.z, acc[i].z);
            acc[i].w = fmaf(a, w.w, acc[i].w);
        }
    }
    #pragma unroll 8
    for (int k = 0; k < 16; k++) {
        float4 w = sW[(32 + k) * 32 + lane];
        #pragma unroll
        for (int i = 0; i < EPG; i++) {
            float a = __shfl_sync(0xffffffffu, te[i], k);
            acc[i].x = fmaf(a, w.x, acc[i].x);
            acc[i].y = fmaf(a, w.y, acc[i].y);
            acc[i].z = fmaf(a, w.z, acc[i].z);
            acc[i].w = fmaf(a, w.w, acc[i].w);
        }
    }

    #pragma unroll
    for (int i = 0; i < EPG; i++) {
        float4 v;
        v.x = fmaxf(acc[i].x, 0.f);
        v.y = fmaxf(acc[i].y, 0.f);
        v.z = fmaxf(acc[i].z, 0.f);
        v.w = fmaxf(acc[i].w, 0.f);
        float* dst = g_agg + (size_t)tgts[i] * 128 + lane * 4;
        asm volatile("red.global.add.v4.f32 [%0], {%1,%2,%3,%4};"
                     :: "l"(dst), "f"(v.x), "f"(v.y), "f"(v.z), "f"(v.w) : "memory");
    }
    if (lane == 0) {
        #pragma unroll
        for (int i = 0; i < EPG; i++) atomicAdd(g_cnt + tgts[i], 1.0f);
    }
}

// ---------------- small elementwise kernels ----------------
__global__ void invc_kernel(int n) {
    int i = blockIdx.x * blockDim.x + threadIdx.x;
    if (i < n) g_invc[i] = 1.0f / fmaxf(g_cnt[i], 1.0f);
}

__global__ void gates_kernel(const float* __restrict__ b_hh, int n) {
    int idx = blockIdx.x * blockDim.x + threadIdx.x;
    if (idx >= n * 128) return;
    int nd = idx >> 7, j = idx & 127;
    float mask = (g_cnt[nd] > 0.f) ? 1.f : 0.f;
    const float* g = g_gi + (size_t)nd * 384;
    float ir = g[j]       + mask * g_cvec[j];
    float iz = g[128 + j] + mask * g_cvec[128 + j];
    float in_ = g[256 + j] + mask * g_cvec[256 + j];
    float r = 1.f / (1.f + expf(-(ir + b_hh[j])));
    float z = 1.f / (1.f + expf(-(iz + b_hh[128 + j])));
    float nn = tanhf(in_ + r * b_hh[256 + j]);
    g_mem[idx] = (1.f - z) * nn;
}

// ---------------- launch ----------------
extern "C" void kernel_launch(void* const* d_in, const int* in_sizes, int n_in,
                              void* d_out, int out_size) {
    const float* x         = (const float*)d_in[0];
    const float* edge_attr = (const float*)d_in[1];
    const float* t_arr     = (const float*)d_in[2];
    const float* time_w    = (const float*)d_in[3];
    const float* time_b    = (const float*)d_in[4];
    const float* msg_w1    = (const float*)d_in[5];
    const float* msg_b1    = (const float*)d_in[6];
    const float* msg_w2    = (const float*)d_in[7];
    const float* msg_b2    = (const float*)d_in[8];
    const float* w_ih      = (const float*)d_in[9];
    // d_in[10] = gru_w_hh: unused (h0 == 0)
    const float* b_ih      = (const float*)d_in[11];
    const float* b_hh      = (const float*)d_in[12];
    const float* out_w     = (const float*)d_in[13];
    const float* out_b     = (const float*)d_in[14];
    const int*   ei        = (const int*)d_in[15];
    float* out = (float*)d_out;

    const int E = in_sizes[15] / 2;
    const int N = in_sizes[0] / NODE_F;
    const int* src = ei;
    const int* tgt = ei + E;

    float *pre, *agg, *cnt, *invc, *Wc, *cvec, *owT, *gi, *mem;
    cudaGetSymbolAddress((void**)&pre,  g_pre);
    cudaGetSymbolAddress((void**)&agg,  g_agg);
    cudaGetSymbolAddress((void**)&cnt,  g_cnt);
    cudaGetSymbolAddress((void**)&invc, g_invc);
    cudaGetSymbolAddress((void**)&Wc,   g_Wc);
    cudaGetSymbolAddress((void**)&cvec, g_cvec);
    cudaGetSymbolAddress((void**)&owT,  g_owT);
    cudaGetSymbolAddress((void**)&gi,   g_gi);
    cudaGetSymbolAddress((void**)&mem,  g_mem);

    cudaMemsetAsync(agg, 0, (size_t)N * 128 * sizeof(float));
    cudaMemsetAsync(cnt, 0, (size_t)N * sizeof(float));

    // prep: Wc = W2 @ W_ih^T, cvec = b2 @ W_ih^T, owT = out_w^T
    {
        int total = 128 * 384 + 384 + 128 * 128;
        prep_kernel<<<(total + 255) / 256, 256>>>(msg_w2, msg_b2, w_ih, out_w);
    }

    // pre = x @ W1a + msg_b1   (W1a = first 128 rows of msg_w1, already [k][n] layout)
    {
        dim3 grid((N + 63) / 64, 1);
        gemm128_kernel<<<grid, 256>>>(x, msg_w1, msg_b1, nullptr, pre, N, 128);
    }

    // edge pipeline: per-edge first-layer + relu + scatter
    {
        int warps = (E + EPG - 1) / EPG;
        int blocks = (warps + 7) / 8;
        edge_kernel<<<blocks, 256>>>(edge_attr, t_arr, src, tgt, msg_w1, time_w, time_b, E);
    }

    invc_kernel<<<(N + 255) / 256, 256>>>(N);

    // gi = (agg * invc) @ Wc + b_ih
    {
        dim3 grid((N + 63) / 64, 3);
        gemm128_kernel<<<grid, 256>>>(agg, Wc, b_ih, invc, gi, N, 384);
    }

    gates_kernel<<<(N * 128 + 255) / 256, 256>>>(b_hh, N);

    // out = mem @ out_w^T + out_b
    {
        dim3 grid((N + 63) / 64, 1);
        gemm128_kernel<<<grid, 256>>>(mem, owT, out_b, nullptr, out, N, 128);
    }
}